// round 1
// baseline (speedup 1.0000x reference)
#include <cuda_runtime.h>
#include <math.h>

// Problem constants (from reference): inputs (4, 8, 24, 24, 64) fp32
//   B = 4, N = 8*24*24 = 4608, C = 64
// out = gamma * softmax(Q Q^T) Q + inputs   (Q = K = V = inputs reshaped (B,N,C))

#define BATCH   4
#define NTOK    4608
#define CDIM    64
#define BM      128
#define BN      128
#define NTILES  (NTOK / BN)   // 36

// Shared memory layout (floats):
//   QsT  [64][128]   k-major Q tile (also reused in epilogue as residual input)
//   KsT  [64][128]   k-major K tile
//   Vs   [128][68]   row-major V tile (pad 64 -> 68 to keep float4 alignment, kill conflicts)
//   PsT  [128][133]  kk-major P (softmax probs) tile, pad 133 to reduce store conflicts
#define QS_OFF  0
#define KS_OFF  (QS_OFF + 64 * 128)
#define VS_LD   68
#define VS_OFF  (KS_OFF + 64 * 128)
#define PS_LD   133
#define PS_OFF  (VS_OFF + 128 * VS_LD)
#define SMEM_FLOATS (PS_OFF + 128 * PS_LD)
#define SMEM_BYTES  (SMEM_FLOATS * 4)

__global__ __launch_bounds__(256, 1)
void attn_flash_f32_kernel(const float* __restrict__ x,
                           const float* __restrict__ gamma_p,
                           float* __restrict__ out)
{
    extern __shared__ float smem[];
    float* QsT = smem + QS_OFF;
    float* KsT = smem + KS_OFF;
    float* Vs  = smem + VS_OFF;
    float* PsT = smem + PS_OFF;

    const int b    = blockIdx.y;
    const int row0 = blockIdx.x * BM;
    const float* xb = x + (size_t)b * NTOK * CDIM;

    const int tid = threadIdx.x;
    const int tx  = tid & 15;   // 0..15 : column group
    const int ty  = tid >> 4;   // 0..15 : row group

    // ---- Load Q tile (128 x 64) transposed into QsT[k][m] ----
    {
        const int r = tid >> 1;            // 0..127
        const int h = (tid & 1) * 32;      // half-row column offset
        const float4* src = (const float4*)(xb + (size_t)(row0 + r) * CDIM + h);
        #pragma unroll
        for (int i = 0; i < 8; i++) {
            float4 v = src[i];
            int c = h + i * 4;
            QsT[(c + 0) * BM + r] = v.x;
            QsT[(c + 1) * BM + r] = v.y;
            QsT[(c + 2) * BM + r] = v.z;
            QsT[(c + 3) * BM + r] = v.w;
        }
    }

    // Online-softmax state. Thread (ty,tx) owns rows ty*8+i; all tx replicas
    // hold identical m/l after shuffle reductions.
    float m_st[8], l_st[8];
    float o[8][4];
    #pragma unroll
    for (int i = 0; i < 8; i++) {
        m_st[i] = -INFINITY;
        l_st[i] = 0.f;
        #pragma unroll
        for (int j = 0; j < 4; j++) o[i][j] = 0.f;
    }

    for (int t = 0; t < NTILES; t++) {
        // Protect KsT/Vs (previous PV reads) before overwriting.
        __syncthreads();

        // ---- Load K/V tile (128 x 64): KsT transposed + Vs row-major ----
        {
            const int r = tid >> 1;
            const int h = (tid & 1) * 32;
            const float4* src = (const float4*)(xb + (size_t)(t * BN + r) * CDIM + h);
            #pragma unroll
            for (int i = 0; i < 8; i++) {
                float4 v = src[i];
                int c = h + i * 4;
                KsT[(c + 0) * BM + r] = v.x;
                KsT[(c + 1) * BM + r] = v.y;
                KsT[(c + 2) * BM + r] = v.z;
                KsT[(c + 3) * BM + r] = v.w;
                *(float4*)&Vs[r * VS_LD + c] = v;
            }
        }
        __syncthreads();

        // ---- S = Q K^T : 8x8 micro-tile per thread ----
        float s[8][8];
        #pragma unroll
        for (int i = 0; i < 8; i++)
            #pragma unroll
            for (int j = 0; j < 8; j++) s[i][j] = 0.f;

        #pragma unroll 4
        for (int k = 0; k < CDIM; k++) {
            float4 a0 = *(const float4*)&QsT[k * BM + ty * 8];
            float4 a1 = *(const float4*)&QsT[k * BM + ty * 8 + 4];
            float4 b0 = *(const float4*)&KsT[k * BM + tx * 8];
            float4 b1 = *(const float4*)&KsT[k * BM + tx * 8 + 4];
            float av[8] = {a0.x, a0.y, a0.z, a0.w, a1.x, a1.y, a1.z, a1.w};
            float bv[8] = {b0.x, b0.y, b0.z, b0.w, b1.x, b1.y, b1.z, b1.w};
            #pragma unroll
            for (int i = 0; i < 8; i++)
                #pragma unroll
                for (int j = 0; j < 8; j++)
                    s[i][j] = fmaf(av[i], bv[j], s[i][j]);
        }

        // ---- Online softmax over this tile ----
        float rmax[8], rsum[8];
        #pragma unroll
        for (int i = 0; i < 8; i++) {
            float m = s[i][0];
            #pragma unroll
            for (int j = 1; j < 8; j++) m = fmaxf(m, s[i][j]);
            rmax[i] = m;
        }
        #pragma unroll
        for (int off = 1; off < 16; off <<= 1) {
            #pragma unroll
            for (int i = 0; i < 8; i++)
                rmax[i] = fmaxf(rmax[i], __shfl_xor_sync(0xffffffffu, rmax[i], off));
        }

        float nm[8], sc[8];
        #pragma unroll
        for (int i = 0; i < 8; i++) {
            nm[i] = fmaxf(m_st[i], rmax[i]);
            sc[i] = __expf(m_st[i] - nm[i]);   // 0 on first tile (-inf - finite)
        }
        #pragma unroll
        for (int i = 0; i < 8; i++) {
            float acc = 0.f;
            #pragma unroll
            for (int j = 0; j < 8; j++) {
                float p = __expf(s[i][j] - nm[i]);
                s[i][j] = p;
                acc += p;
            }
            rsum[i] = acc;
        }
        #pragma unroll
        for (int off = 1; off < 16; off <<= 1) {
            #pragma unroll
            for (int i = 0; i < 8; i++)
                rsum[i] += __shfl_xor_sync(0xffffffffu, rsum[i], off);
        }
        #pragma unroll
        for (int i = 0; i < 8; i++) {
            l_st[i] = l_st[i] * sc[i] + rsum[i];
            m_st[i] = nm[i];
            #pragma unroll
            for (int j = 0; j < 4; j++) o[i][j] *= sc[i];
        }

        // ---- Stage P transposed: PsT[kk][m] ----
        #pragma unroll
        for (int j = 0; j < 8; j++) {
            #pragma unroll
            for (int i = 0; i < 8; i++)
                PsT[(tx * 8 + j) * PS_LD + ty * 8 + i] = s[i][j];
        }
        __syncthreads();

        // ---- O += P V : 8x4 micro-tile per thread over kk = 0..127 ----
        #pragma unroll 2
        for (int kk = 0; kk < BN; kk++) {
            float4 bv = *(const float4*)&Vs[kk * VS_LD + tx * 4];
            const float* pa = &PsT[kk * PS_LD + ty * 8];
            #pragma unroll
            for (int i = 0; i < 8; i++) {
                float a = pa[i];
                o[i][0] = fmaf(a, bv.x, o[i][0]);
                o[i][1] = fmaf(a, bv.y, o[i][1]);
                o[i][2] = fmaf(a, bv.z, o[i][2]);
                o[i][3] = fmaf(a, bv.w, o[i][3]);
            }
        }
    }

    // ---- Epilogue: out = gamma * (O / l) + input  (input read back from QsT) ----
    const float g = *gamma_p;
    #pragma unroll
    for (int i = 0; i < 8; i++) {
        const int m = ty * 8 + i;
        const int r = row0 + m;
        const float invl = 1.f / l_st[i];
        float4 res;
        const int c = tx * 4;
        res.x = fmaf(g, o[i][0] * invl, QsT[(c + 0) * BM + m]);
        res.y = fmaf(g, o[i][1] * invl, QsT[(c + 1) * BM + m]);
        res.z = fmaf(g, o[i][2] * invl, QsT[(c + 2) * BM + m]);
        res.w = fmaf(g, o[i][3] * invl, QsT[(c + 3) * BM + m]);
        *(float4*)(out + ((size_t)b * NTOK + r) * CDIM + c) = res;
    }
}

extern "C" void kernel_launch(void* const* d_in, const int* in_sizes, int n_in,
                              void* d_out, int out_size)
{
    const float* x     = (const float*)d_in[0];   // inputs (4,8,24,24,64) fp32
    const float* gamma = (const float*)d_in[1];   // gamma (1,) fp32
    float* out = (float*)d_out;

    cudaFuncSetAttribute(attn_flash_f32_kernel,
                         cudaFuncAttributeMaxDynamicSharedMemorySize, SMEM_BYTES);

    dim3 grid(NTOK / BM, BATCH);   // (36, 4) = 144 CTAs ~ one wave on 148 SMs
    attn_flash_f32_kernel<<<grid, 256, SMEM_BYTES>>>(x, gamma, out);
}

// round 4
// speedup vs baseline: 2.8333x; 2.8333x over previous
#include <cuda_runtime.h>
#include <cuda_fp16.h>
#include <math.h>
#include <cstdint>

// Problem: inputs (4, 8, 24, 24, 64) fp32 -> B=4, N=4608, C=64
// out = gamma * softmax(Q Q^T) Q + inputs,  Q = K = V = inputs.reshape(B,N,C)
//
// Flash attention with online softmax; fp16x3 (2-term split, 3 MMA passes:
// hi*hi + hi*lo + lo*hi) on both GEMMs via mma.sync.m16n8k16.

#define BATCH   4
#define NTOK    4608
#define CDIM    64
#define BM      128
#define BN      128
#define NTILES  (NTOK / BN)   // 36

// SMEM half-tile row stride: 64 + 8 pad halves (conflict-free ldmatrix)
#define LDH 72

// byte offsets in dynamic SMEM
#define QH_B   0
#define QL_B   18432
#define KH_B   36864
#define KL_B   55296
#define SMEM_DYN (73728)

// ---------------- PTX helpers ----------------
__device__ __forceinline__ uint32_t smem_u32(const void* p) {
    uint32_t a;
    asm("{ .reg .u64 t; cvta.to.shared.u64 t, %1; cvt.u32.u64 %0, t; }" : "=r"(a) : "l"(p));
    return a;
}

#define LDSM_X4(r0, r1, r2, r3, a) \
    asm volatile("ldmatrix.sync.aligned.m8n8.x4.shared.b16 {%0,%1,%2,%3}, [%4];" \
        : "=r"(r0), "=r"(r1), "=r"(r2), "=r"(r3) : "r"(a))
#define LDSM_X2(r0, r1, a) \
    asm volatile("ldmatrix.sync.aligned.m8n8.x2.shared.b16 {%0,%1}, [%2];" \
        : "=r"(r0), "=r"(r1) : "r"(a))
#define LDSM_X2T(r0, r1, a) \
    asm volatile("ldmatrix.sync.aligned.m8n8.x2.trans.shared.b16 {%0,%1}, [%2];" \
        : "=r"(r0), "=r"(r1) : "r"(a))

#define MMA16816(c, a0, a1, a2, a3, b0, b1) \
    asm volatile("mma.sync.aligned.m16n8k16.row.col.f32.f16.f16.f32 " \
        "{%0,%1,%2,%3}, {%4,%5,%6,%7}, {%8,%9}, {%0,%1,%2,%3};" \
        : "+f"((c)[0]), "+f"((c)[1]), "+f"((c)[2]), "+f"((c)[3]) \
        : "r"(a0), "r"(a1), "r"(a2), "r"(a3), "r"(b0), "r"(b1))

__device__ __forceinline__ uint32_t h2u(half2 h) { return *(uint32_t*)&h; }

// ---------------- fused attention ----------------
__global__ __launch_bounds__(256, 1)
void attn_mma_f16x3_kernel(const float* __restrict__ x,
                           const float* __restrict__ gamma_p,
                           float* __restrict__ out)
{
    extern __shared__ char sm[];
    const uint32_t smb = smem_u32(sm);

    const int tid  = threadIdx.x;
    const int w    = tid >> 5;
    const int lane = tid & 31;
    const int g    = lane >> 2;    // row within 16-row warp tile (and +8)
    const int t4   = lane & 3;     // col group

    const int b    = blockIdx.y;
    const int row0 = blockIdx.x * BM;
    const float* xb = x + (size_t)b * NTOK * CDIM;

    // ---- load Q tile (this CTA's 128 rows): split fp32 -> hi/lo fp16
    {
        const int r  = tid >> 1;
        const int hh = (tid & 1) << 5;
        const float4* src = (const float4*)(xb + (size_t)(row0 + r) * CDIM + hh);
        #pragma unroll
        for (int i = 0; i < 8; i++) {
            float4 v = src[i];
            int c = hh + i * 4;
            half2 h01 = __floats2half2_rn(v.x, v.y);
            half2 h23 = __floats2half2_rn(v.z, v.w);
            half2 l01 = __floats2half2_rn(v.x - __low2float(h01), v.y - __high2float(h01));
            half2 l23 = __floats2half2_rn(v.z - __low2float(h23), v.w - __high2float(h23));
            *(half2*)(sm + QH_B + (r * LDH + c) * 2)     = h01;
            *(half2*)(sm + QH_B + (r * LDH + c + 2) * 2) = h23;
            *(half2*)(sm + QL_B + (r * LDH + c) * 2)     = l01;
            *(half2*)(sm + QL_B + (r * LDH + c + 2) * 2) = l23;
        }
    }
    __syncthreads();

    // ---- preload Q A-fragments (4 k-steps x 4 regs, hi & lo)
    uint32_t qh[16], ql[16];
    {
        const int qrow = w * 16 + ((lane >> 3) & 1) * 8 + (lane & 7);
        const int qchb = (lane >> 4) * 8;
        #pragma unroll
        for (int kb = 0; kb < 4; kb++) {
            uint32_t off = (uint32_t)(qrow * LDH + kb * 16 + qchb) * 2;
            LDSM_X4(qh[kb*4], qh[kb*4+1], qh[kb*4+2], qh[kb*4+3], smb + QH_B + off);
            LDSM_X4(ql[kb*4], ql[kb*4+1], ql[kb*4+2], ql[kb*4+3], smb + QL_B + off);
        }
    }

    // online softmax state for the two rows this thread touches (g, g+8)
    float m1 = -INFINITY, m2 = -INFINITY;
    float lsum1 = 0.f, lsum2 = 0.f;
    float o[8][4];
    #pragma unroll
    for (int i = 0; i < 8; i++)
        #pragma unroll
        for (int j = 0; j < 4; j++) o[i][j] = 0.f;

    // lane-invariant ldmatrix address parts
    const int l15 = lane & 15;
    const uint32_t kfrag_inv = (uint32_t)((l15 & 7) * LDH + (l15 >> 3) * 8) * 2; // K B-frags
    const uint32_t vfrag_inv = (uint32_t)(l15 * LDH) * 2;                        // V B-frags (trans)

    for (int t = 0; t < NTILES; t++) {
        __syncthreads();   // protect KV tile from previous iteration's readers

        // ---- load KV tile (tokens t*128 ..): hi/lo fp16
        {
            const int r  = tid >> 1;
            const int hh = (tid & 1) << 5;
            const float4* src = (const float4*)(xb + (size_t)(t * BN + r) * CDIM + hh);
            #pragma unroll
            for (int i = 0; i < 8; i++) {
                float4 v = src[i];
                int c = hh + i * 4;
                half2 h01 = __floats2half2_rn(v.x, v.y);
                half2 h23 = __floats2half2_rn(v.z, v.w);
                half2 l01 = __floats2half2_rn(v.x - __low2float(h01), v.y - __high2float(h01));
                half2 l23 = __floats2half2_rn(v.z - __low2float(h23), v.w - __high2float(h23));
                *(half2*)(sm + KH_B + (r * LDH + c) * 2)     = h01;
                *(half2*)(sm + KH_B + (r * LDH + c + 2) * 2) = h23;
                *(half2*)(sm + KL_B + (r * LDH + c) * 2)     = l01;
                *(half2*)(sm + KL_B + (r * LDH + c + 2) * 2) = l23;
            }
        }
        __syncthreads();

        // ---- S = Q K^T (fp16x3): C[16 n-tiles][4]
        float c[16][4];
        #pragma unroll
        for (int nb = 0; nb < 16; nb++) {
            c[nb][0] = 0.f; c[nb][1] = 0.f; c[nb][2] = 0.f; c[nb][3] = 0.f;
        }
        #pragma unroll
        for (int nb = 0; nb < 16; nb++) {
            #pragma unroll
            for (int kb = 0; kb < 4; kb++) {
                uint32_t off = (uint32_t)(nb * 8 * LDH + kb * 16) * 2 + kfrag_inv;
                uint32_t bh0, bh1, bl0, bl1;
                LDSM_X2(bh0, bh1, smb + KH_B + off);
                LDSM_X2(bl0, bl1, smb + KL_B + off);
                MMA16816(c[nb], qh[kb*4], qh[kb*4+1], qh[kb*4+2], qh[kb*4+3], bh0, bh1);
                MMA16816(c[nb], qh[kb*4], qh[kb*4+1], qh[kb*4+2], qh[kb*4+3], bl0, bl1);
                MMA16816(c[nb], ql[kb*4], ql[kb*4+1], ql[kb*4+2], ql[kb*4+3], bh0, bh1);
            }
        }

        // ---- online softmax: true tile row max, rescale, exp, pack fp16 hi/lo
        float tm1 = c[0][0], tm2 = c[0][2];
        #pragma unroll
        for (int nb = 0; nb < 16; nb++) {
            tm1 = fmaxf(tm1, fmaxf(c[nb][0], c[nb][1]));
            tm2 = fmaxf(tm2, fmaxf(c[nb][2], c[nb][3]));
        }
        #pragma unroll
        for (int off = 1; off < 4; off <<= 1) {
            tm1 = fmaxf(tm1, __shfl_xor_sync(0xffffffffu, tm1, off));
            tm2 = fmaxf(tm2, __shfl_xor_sync(0xffffffffu, tm2, off));
        }
        const float nm1 = fmaxf(m1, tm1);
        const float nm2 = fmaxf(m2, tm2);
        const float sc1 = __expf(m1 - nm1);   // 0 on first tile
        const float sc2 = __expf(m2 - nm2);
        m1 = nm1; m2 = nm2;
        lsum1 *= sc1; lsum2 *= sc2;
        #pragma unroll
        for (int i = 0; i < 8; i++) {
            o[i][0] *= sc1; o[i][1] *= sc1;
            o[i][2] *= sc2; o[i][3] *= sc2;
        }

        uint32_t ph[32], pl[32];
        #pragma unroll
        for (int nb = 0; nb < 16; nb++) {
            float p0 = __expf(c[nb][0] - nm1);
            float p1 = __expf(c[nb][1] - nm1);
            float p2 = __expf(c[nb][2] - nm2);
            float p3 = __expf(c[nb][3] - nm2);
            lsum1 += p0 + p1;
            lsum2 += p2 + p3;
            half2 h01 = __floats2half2_rn(p0, p1);
            half2 h23 = __floats2half2_rn(p2, p3);
            half2 l01 = __floats2half2_rn(p0 - __low2float(h01), p1 - __high2float(h01));
            half2 l23 = __floats2half2_rn(p2 - __low2float(h23), p3 - __high2float(h23));
            ph[nb*2]   = h2u(h01);  ph[nb*2+1] = h2u(h23);
            pl[nb*2]   = h2u(l01);  pl[nb*2+1] = h2u(l23);
        }

        // ---- O += P V (fp16x3): A = P fragments (registers), B = V via ldmatrix.trans
        #pragma unroll
        for (int kb = 0; kb < 8; kb++) {
            uint32_t a0h = ph[kb*4], a1h = ph[kb*4+1], a2h = ph[kb*4+2], a3h = ph[kb*4+3];
            uint32_t a0l = pl[kb*4], a1l = pl[kb*4+1], a2l = pl[kb*4+2], a3l = pl[kb*4+3];
            #pragma unroll
            for (int nb2 = 0; nb2 < 8; nb2++) {
                uint32_t off = (uint32_t)(kb * 16 * LDH + nb2 * 8) * 2 + vfrag_inv;
                uint32_t vh0, vh1, vl0, vl1;
                LDSM_X2T(vh0, vh1, smb + KH_B + off);
                LDSM_X2T(vl0, vl1, smb + KL_B + off);
                MMA16816(o[nb2], a0h, a1h, a2h, a3h, vh0, vh1);
                MMA16816(o[nb2], a0h, a1h, a2h, a3h, vl0, vl1);
                MMA16816(o[nb2], a0l, a1l, a2l, a3l, vh0, vh1);
            }
        }
    }

    // ---- reduce row sums across the 4 lanes of each row group
    #pragma unroll
    for (int off = 1; off < 4; off <<= 1) {
        lsum1 += __shfl_xor_sync(0xffffffffu, lsum1, off);
        lsum2 += __shfl_xor_sync(0xffffffffu, lsum2, off);
    }
    const float invl1 = 1.f / lsum1;
    const float invl2 = 1.f / lsum2;

    // ---- epilogue: out = gamma * O/l + x
    {
        const float gm = *gamma_p;
        const int r1 = row0 + w * 16 + g;
        const int r2 = r1 + 8;
        #pragma unroll
        for (int nb2 = 0; nb2 < 8; nb2++) {
            const int col = nb2 * 8 + t4 * 2;
            float2 x1 = *(const float2*)(xb + (size_t)r1 * CDIM + col);
            float2 x2v = *(const float2*)(xb + (size_t)r2 * CDIM + col);
            float2 o1, o2;
            o1.x = fmaf(gm, o[nb2][0] * invl1, x1.x);
            o1.y = fmaf(gm, o[nb2][1] * invl1, x1.y);
            o2.x = fmaf(gm, o[nb2][2] * invl2, x2v.x);
            o2.y = fmaf(gm, o[nb2][3] * invl2, x2v.y);
            *(float2*)(out + ((size_t)b * NTOK + r1) * CDIM + col) = o1;
            *(float2*)(out + ((size_t)b * NTOK + r2) * CDIM + col) = o2;
        }
    }
}

extern "C" void kernel_launch(void* const* d_in, const int* in_sizes, int n_in,
                              void* d_out, int out_size)
{
    const float* x     = (const float*)d_in[0];
    const float* gamma = (const float*)d_in[1];
    float* out = (float*)d_out;

    cudaFuncSetAttribute(attn_mma_f16x3_kernel,
                         cudaFuncAttributeMaxDynamicSharedMemorySize, SMEM_DYN);

    dim3 grid(NTOK / BM, BATCH);   // (36, 4) = 144 CTAs ~ one wave
    attn_mma_f16x3_kernel<<<grid, 256, SMEM_DYN>>>(x, gamma, out);
}

// round 5
// speedup vs baseline: 3.3596x; 1.1857x over previous
#include <cuda_runtime.h>
#include <cuda_fp16.h>
#include <math.h>
#include <cstdint>

// Problem: inputs (4, 8, 24, 24, 64) fp32 -> B=4, N=4608, C=64
// out = gamma * softmax(Q Q^T) Q + inputs,  Q = K = V = inputs.reshape(B,N,C)
//
// Flash attention, online softmax, mma.sync.m16n8k16:
//   S  = Q K^T : fp16x3 (qh*kh + qh*kl + ql*kh)
//   O += P V   : exact-P fp16x2 (ph*vh + pl*vh); V-lo dropped (~1e-4 rel)
// KV tiles double-buffered in SMEM; 1 syncthreads per tile.

#define BATCH   4
#define NTOK    4608
#define CDIM    64
#define BM      128
#define BN      128
#define NTILES  (NTOK / BN)   // 36

#define LDH 72                // half-tile row stride (64 + 8 pad)

// byte offsets in dynamic SMEM
#define QH_B    0
#define QL_B    18432
#define KB_H(buf) (36864 + (buf) * 36864)
#define KB_L(buf) (KB_H(buf) + 18432)
#define SMEM_DYN  (36864 + 2 * 36864)   // 110592

// ---------------- PTX helpers ----------------
__device__ __forceinline__ uint32_t smem_u32(const void* p) {
    uint32_t a;
    asm("{ .reg .u64 t; cvta.to.shared.u64 t, %1; cvt.u32.u64 %0, t; }" : "=r"(a) : "l"(p));
    return a;
}

#define LDSM_X4(r0, r1, r2, r3, a) \
    asm volatile("ldmatrix.sync.aligned.m8n8.x4.shared.b16 {%0,%1,%2,%3}, [%4];" \
        : "=r"(r0), "=r"(r1), "=r"(r2), "=r"(r3) : "r"(a))
#define LDSM_X4T(r0, r1, r2, r3, a) \
    asm volatile("ldmatrix.sync.aligned.m8n8.x4.trans.shared.b16 {%0,%1,%2,%3}, [%4];" \
        : "=r"(r0), "=r"(r1), "=r"(r2), "=r"(r3) : "r"(a))

#define MMA16816(c, a0, a1, a2, a3, b0, b1) \
    asm volatile("mma.sync.aligned.m16n8k16.row.col.f32.f16.f16.f32 " \
        "{%0,%1,%2,%3}, {%4,%5,%6,%7}, {%8,%9}, {%0,%1,%2,%3};" \
        : "+f"((c)[0]), "+f"((c)[1]), "+f"((c)[2]), "+f"((c)[3]) \
        : "r"(a0), "r"(a1), "r"(a2), "r"(a3), "r"(b0), "r"(b1))

__device__ __forceinline__ uint32_t h2u(half2 h) { return *(uint32_t*)&h; }

// split fp32x4 -> hi/lo fp16 and store to (r, c) in the hi/lo half-tiles
__device__ __forceinline__ void cvt_store(char* sm_h, char* sm_l, int r, int c, float4 v) {
    half2 h01 = __floats2half2_rn(v.x, v.y);
    half2 h23 = __floats2half2_rn(v.z, v.w);
    half2 l01 = __floats2half2_rn(v.x - __low2float(h01), v.y - __high2float(h01));
    half2 l23 = __floats2half2_rn(v.z - __low2float(h23), v.w - __high2float(h23));
    *(half2*)(sm_h + (r * LDH + c) * 2)     = h01;
    *(half2*)(sm_h + (r * LDH + c + 2) * 2) = h23;
    *(half2*)(sm_l + (r * LDH + c) * 2)     = l01;
    *(half2*)(sm_l + (r * LDH + c + 2) * 2) = l23;
}

// ---------------- fused attention ----------------
__global__ __launch_bounds__(256, 1)
void attn_mma_pipe_kernel(const float* __restrict__ x,
                          const float* __restrict__ gamma_p,
                          float* __restrict__ out)
{
    extern __shared__ char sm[];
    const uint32_t smb = smem_u32(sm);

    const int tid  = threadIdx.x;
    const int w    = tid >> 5;
    const int lane = tid & 31;
    const int g    = lane >> 2;    // row within 16-row warp tile (and +8)
    const int t4   = lane & 3;     // col group

    const int b    = blockIdx.y;
    const int row0 = blockIdx.x * BM;
    const float* xb = x + (size_t)b * NTOK * CDIM;

    const int rload = tid >> 1;
    const int hload = (tid & 1) << 5;

    // ---- preamble: load Q tile + KV tile 0
    {
        const float4* qsrc = (const float4*)(xb + (size_t)(row0 + rload) * CDIM + hload);
        const float4* ksrc = (const float4*)(xb + (size_t)rload * CDIM + hload);
        #pragma unroll
        for (int i = 0; i < 8; i++) {
            cvt_store(sm + QH_B, sm + QL_B, rload, hload + i * 4, qsrc[i]);
            cvt_store(sm + KB_H(0), sm + KB_L(0), rload, hload + i * 4, ksrc[i]);
        }
    }
    __syncthreads();

    // ---- preload Q A-fragments (4 k-steps x 4 regs, hi & lo)
    uint32_t qh[16], ql[16];
    {
        const int qrow = w * 16 + ((lane >> 3) & 1) * 8 + (lane & 7);
        const int qchb = (lane >> 4) * 8;
        #pragma unroll
        for (int kb = 0; kb < 4; kb++) {
            uint32_t off = (uint32_t)(qrow * LDH + kb * 16 + qchb) * 2;
            LDSM_X4(qh[kb*4], qh[kb*4+1], qh[kb*4+2], qh[kb*4+3], smb + QH_B + off);
            LDSM_X4(ql[kb*4], ql[kb*4+1], ql[kb*4+2], ql[kb*4+3], smb + QL_B + off);
        }
    }

    // online softmax state for the two rows this thread touches (g, g+8)
    float m1 = -INFINITY, m2 = -INFINITY;
    float lsum1 = 0.f, lsum2 = 0.f;
    float o[8][4];
    #pragma unroll
    for (int i = 0; i < 8; i++)
        #pragma unroll
        for (int j = 0; j < 4; j++) o[i][j] = 0.f;

    // lane-invariant ldmatrix address parts (x4 forms: lanes 16-31 -> 2nd n-tile)
    const int l15 = lane & 15;
    const uint32_t kfrag4_inv = (uint32_t)((l15 & 7) * LDH + (l15 >> 3) * 8
                                           + (lane >> 4) * 8 * LDH) * 2;   // K B-frags
    const uint32_t vfrag4_inv = (uint32_t)(l15 * LDH) * 2 + (uint32_t)(lane >> 4) * 16; // V trans

    for (int t = 0; t < NTILES; t++) {
        const int cur = t & 1, nxt = cur ^ 1;
        const uint32_t kh = smb + KB_H(cur);
        const uint32_t kl = smb + KB_L(cur);

        // ---- prefetch next KV tile into registers
        float4 pre[8];
        if (t + 1 < NTILES) {
            const float4* src = (const float4*)(xb + (size_t)((t + 1) * BN + rload) * CDIM + hload);
            #pragma unroll
            for (int i = 0; i < 8; i++) pre[i] = src[i];
        }

        // ---- S = Q K^T (fp16x3)
        float c[16][4];
        #pragma unroll
        for (int nb = 0; nb < 16; nb++) {
            c[nb][0] = 0.f; c[nb][1] = 0.f; c[nb][2] = 0.f; c[nb][3] = 0.f;
        }
        #pragma unroll
        for (int nbp = 0; nbp < 8; nbp++) {
            #pragma unroll
            for (int kb = 0; kb < 4; kb++) {
                uint32_t off = (uint32_t)(nbp * 16 * LDH + kb * 16) * 2 + kfrag4_inv;
                uint32_t bh0, bh1, bh2, bh3, bl0, bl1, bl2, bl3;
                LDSM_X4(bh0, bh1, bh2, bh3, kh + off);
                LDSM_X4(bl0, bl1, bl2, bl3, kl + off);
                MMA16816(c[2*nbp],   qh[kb*4], qh[kb*4+1], qh[kb*4+2], qh[kb*4+3], bh0, bh1);
                MMA16816(c[2*nbp],   qh[kb*4], qh[kb*4+1], qh[kb*4+2], qh[kb*4+3], bl0, bl1);
                MMA16816(c[2*nbp],   ql[kb*4], ql[kb*4+1], ql[kb*4+2], ql[kb*4+3], bh0, bh1);
                MMA16816(c[2*nbp+1], qh[kb*4], qh[kb*4+1], qh[kb*4+2], qh[kb*4+3], bh2, bh3);
                MMA16816(c[2*nbp+1], qh[kb*4], qh[kb*4+1], qh[kb*4+2], qh[kb*4+3], bl2, bl3);
                MMA16816(c[2*nbp+1], ql[kb*4], ql[kb*4+1], ql[kb*4+2], ql[kb*4+3], bh2, bh3);
            }
        }

        // ---- store prefetched tile to the other buffer (frees pre regs)
        if (t + 1 < NTILES) {
            #pragma unroll
            for (int i = 0; i < 8; i++)
                cvt_store(sm + KB_H(nxt), sm + KB_L(nxt), rload, hload + i * 4, pre[i]);
        }

        // ---- online softmax: tile row max, rescale state
        float tm1 = c[0][0], tm2 = c[0][2];
        #pragma unroll
        for (int nb = 0; nb < 16; nb++) {
            tm1 = fmaxf(tm1, fmaxf(c[nb][0], c[nb][1]));
            tm2 = fmaxf(tm2, fmaxf(c[nb][2], c[nb][3]));
        }
        #pragma unroll
        for (int off = 1; off < 4; off <<= 1) {
            tm1 = fmaxf(tm1, __shfl_xor_sync(0xffffffffu, tm1, off));
            tm2 = fmaxf(tm2, __shfl_xor_sync(0xffffffffu, tm2, off));
        }
        const float nm1 = fmaxf(m1, tm1);
        const float nm2 = fmaxf(m2, tm2);
        const float sc1 = __expf(m1 - nm1);   // 0 on first tile
        const float sc2 = __expf(m2 - nm2);
        m1 = nm1; m2 = nm2;
        lsum1 *= sc1; lsum2 *= sc2;
        #pragma unroll
        for (int i = 0; i < 8; i++) {
            o[i][0] *= sc1; o[i][1] *= sc1;
            o[i][2] *= sc2; o[i][3] *= sc2;
        }

        // ---- per k-chunk: exp + pack P (hi/lo), then PV MMAs (V hi only)
        #pragma unroll
        for (int kb = 0; kb < 8; kb++) {
            const int nbA = 2 * kb, nbB = 2 * kb + 1;
            float pA0 = __expf(c[nbA][0] - nm1);
            float pA1 = __expf(c[nbA][1] - nm1);
            float pA2 = __expf(c[nbA][2] - nm2);
            float pA3 = __expf(c[nbA][3] - nm2);
            float pB0 = __expf(c[nbB][0] - nm1);
            float pB1 = __expf(c[nbB][1] - nm1);
            float pB2 = __expf(c[nbB][2] - nm2);
            float pB3 = __expf(c[nbB][3] - nm2);
            lsum1 += pA0 + pA1 + pB0 + pB1;
            lsum2 += pA2 + pA3 + pB2 + pB3;
            half2 hA01 = __floats2half2_rn(pA0, pA1);
            half2 hA23 = __floats2half2_rn(pA2, pA3);
            half2 hB01 = __floats2half2_rn(pB0, pB1);
            half2 hB23 = __floats2half2_rn(pB2, pB3);
            half2 lA01 = __floats2half2_rn(pA0 - __low2float(hA01), pA1 - __high2float(hA01));
            half2 lA23 = __floats2half2_rn(pA2 - __low2float(hA23), pA3 - __high2float(hA23));
            half2 lB01 = __floats2half2_rn(pB0 - __low2float(hB01), pB1 - __high2float(hB01));
            half2 lB23 = __floats2half2_rn(pB2 - __low2float(hB23), pB3 - __high2float(hB23));
            const uint32_t a0h = h2u(hA01), a1h = h2u(hA23), a2h = h2u(hB01), a3h = h2u(hB23);
            const uint32_t a0l = h2u(lA01), a1l = h2u(lA23), a2l = h2u(lB01), a3l = h2u(lB23);

            #pragma unroll
            for (int np = 0; np < 4; np++) {
                uint32_t off = (uint32_t)(kb * 16 * LDH + np * 16) * 2 + vfrag4_inv;
                uint32_t v0, v1, v2, v3;
                LDSM_X4T(v0, v1, v2, v3, kh + off);
                MMA16816(o[2*np],   a0h, a1h, a2h, a3h, v0, v1);
                MMA16816(o[2*np],   a0l, a1l, a2l, a3l, v0, v1);
                MMA16816(o[2*np+1], a0h, a1h, a2h, a3h, v2, v3);
                MMA16816(o[2*np+1], a0l, a1l, a2l, a3l, v2, v3);
            }
        }

        __syncthreads();   // buffer nxt fully written; cur free for overwrite next iter
    }

    // ---- reduce row sums across the 4 lanes of each row group
    #pragma unroll
    for (int off = 1; off < 4; off <<= 1) {
        lsum1 += __shfl_xor_sync(0xffffffffu, lsum1, off);
        lsum2 += __shfl_xor_sync(0xffffffffu, lsum2, off);
    }
    const float invl1 = 1.f / lsum1;
    const float invl2 = 1.f / lsum2;

    // ---- epilogue: out = gamma * O/l + x
    {
        const float gm = *gamma_p;
        const int r1 = row0 + w * 16 + g;
        const int r2 = r1 + 8;
        #pragma unroll
        for (int nb2 = 0; nb2 < 8; nb2++) {
            const int col = nb2 * 8 + t4 * 2;
            float2 x1  = *(const float2*)(xb + (size_t)r1 * CDIM + col);
            float2 x2v = *(const float2*)(xb + (size_t)r2 * CDIM + col);
            float2 o1, o2;
            o1.x = fmaf(gm, o[nb2][0] * invl1, x1.x);
            o1.y = fmaf(gm, o[nb2][1] * invl1, x1.y);
            o2.x = fmaf(gm, o[nb2][2] * invl2, x2v.x);
            o2.y = fmaf(gm, o[nb2][3] * invl2, x2v.y);
            *(float2*)(out + ((size_t)b * NTOK + r1) * CDIM + col) = o1;
            *(float2*)(out + ((size_t)b * NTOK + r2) * CDIM + col) = o2;
        }
    }
}

extern "C" void kernel_launch(void* const* d_in, const int* in_sizes, int n_in,
                              void* d_out, int out_size)
{
    const float* x     = (const float*)d_in[0];
    const float* gamma = (const float*)d_in[1];
    float* out = (float*)d_out;

    cudaFuncSetAttribute(attn_mma_pipe_kernel,
                         cudaFuncAttributeMaxDynamicSharedMemorySize, SMEM_DYN);

    dim3 grid(NTOK / BM, BATCH);   // (36, 4) = 144 CTAs ~ one wave
    attn_mma_pipe_kernel<<<grid, 256, SMEM_DYN>>>(x, gamma, out);
}

// round 6
// speedup vs baseline: 3.4304x; 1.0211x over previous
#include <cuda_runtime.h>
#include <cuda_fp16.h>
#include <math.h>
#include <cstdint>

// Problem: inputs (4, 8, 24, 24, 64) fp32 -> B=4, N=4608, C=64
// out = gamma * softmax(Q Q^T) Q + inputs,  Q = K = V = inputs.reshape(B,N,C)
//
// Flash attention, online softmax, mma.sync.m16n8k16:
//   S  = Q K^T : fp16x3 (qh*kh + qh*kl + ql*kh)
//   O += P V   : exact-P fp16x2 (ph*vh + pl*vh)
// KV double-buffered; MMAs interleaved across accumulators to break
// same-accumulator dependency chains; P exp/pack pipelined one chunk ahead.

#define BATCH   4
#define NTOK    4608
#define CDIM    64
#define BM      128
#define BN      128
#define NTILES  (NTOK / BN)   // 36

#define LDH 72                // half-tile row stride (64 + 8 pad)

#define QH_B    0
#define QL_B    18432
#define KB_H(buf) (36864 + (buf) * 36864)
#define KB_L(buf) (KB_H(buf) + 18432)
#define SMEM_DYN  (36864 + 2 * 36864)   // 110592

// ---------------- PTX helpers ----------------
__device__ __forceinline__ uint32_t smem_u32(const void* p) {
    uint32_t a;
    asm("{ .reg .u64 t; cvta.to.shared.u64 t, %1; cvt.u32.u64 %0, t; }" : "=r"(a) : "l"(p));
    return a;
}

#define LDSM_X4(r0, r1, r2, r3, a) \
    asm volatile("ldmatrix.sync.aligned.m8n8.x4.shared.b16 {%0,%1,%2,%3}, [%4];" \
        : "=r"(r0), "=r"(r1), "=r"(r2), "=r"(r3) : "r"(a))
#define LDSM_X4T(r0, r1, r2, r3, a) \
    asm volatile("ldmatrix.sync.aligned.m8n8.x4.trans.shared.b16 {%0,%1,%2,%3}, [%4];" \
        : "=r"(r0), "=r"(r1), "=r"(r2), "=r"(r3) : "r"(a))

#define MMA16816(c, a0, a1, a2, a3, b0, b1) \
    asm volatile("mma.sync.aligned.m16n8k16.row.col.f32.f16.f16.f32 " \
        "{%0,%1,%2,%3}, {%4,%5,%6,%7}, {%8,%9}, {%0,%1,%2,%3};" \
        : "+f"((c)[0]), "+f"((c)[1]), "+f"((c)[2]), "+f"((c)[3]) \
        : "r"(a0), "r"(a1), "r"(a2), "r"(a3), "r"(b0), "r"(b1))

__device__ __forceinline__ uint32_t h2u(half2 h) { return *(uint32_t*)&h; }

__device__ __forceinline__ void cvt_store(char* sm_h, char* sm_l, int r, int c, float4 v) {
    half2 h01 = __floats2half2_rn(v.x, v.y);
    half2 h23 = __floats2half2_rn(v.z, v.w);
    half2 l01 = __floats2half2_rn(v.x - __low2float(h01), v.y - __high2float(h01));
    half2 l23 = __floats2half2_rn(v.z - __low2float(h23), v.w - __high2float(h23));
    *(half2*)(sm_h + (r * LDH + c) * 2)     = h01;
    *(half2*)(sm_h + (r * LDH + c + 2) * 2) = h23;
    *(half2*)(sm_l + (r * LDH + c) * 2)     = l01;
    *(half2*)(sm_l + (r * LDH + c + 2) * 2) = l23;
}

// ---------------- fused attention ----------------
__global__ __launch_bounds__(256, 1)
void attn_mma_ilp_kernel(const float* __restrict__ x,
                         const float* __restrict__ gamma_p,
                         float* __restrict__ out)
{
    extern __shared__ char sm[];
    const uint32_t smb = smem_u32(sm);

    const int tid  = threadIdx.x;
    const int w    = tid >> 5;
    const int lane = tid & 31;
    const int g    = lane >> 2;
    const int t4   = lane & 3;

    const int b    = blockIdx.y;
    const int row0 = blockIdx.x * BM;
    const float* xb = x + (size_t)b * NTOK * CDIM;

    const int rload = tid >> 1;
    const int hload = (tid & 1) << 5;

    // ---- preamble: load Q tile + KV tile 0
    {
        const float4* qsrc = (const float4*)(xb + (size_t)(row0 + rload) * CDIM + hload);
        const float4* ksrc = (const float4*)(xb + (size_t)rload * CDIM + hload);
        #pragma unroll
        for (int i = 0; i < 8; i++) {
            cvt_store(sm + QH_B, sm + QL_B, rload, hload + i * 4, qsrc[i]);
            cvt_store(sm + KB_H(0), sm + KB_L(0), rload, hload + i * 4, ksrc[i]);
        }
    }
    __syncthreads();

    // ---- preload Q A-fragments
    uint32_t qh[16], ql[16];
    {
        const int qrow = w * 16 + ((lane >> 3) & 1) * 8 + (lane & 7);
        const int qchb = (lane >> 4) * 8;
        #pragma unroll
        for (int kb = 0; kb < 4; kb++) {
            uint32_t off = (uint32_t)(qrow * LDH + kb * 16 + qchb) * 2;
            LDSM_X4(qh[kb*4], qh[kb*4+1], qh[kb*4+2], qh[kb*4+3], smb + QH_B + off);
            LDSM_X4(ql[kb*4], ql[kb*4+1], ql[kb*4+2], ql[kb*4+3], smb + QL_B + off);
        }
    }

    float m1 = -INFINITY, m2 = -INFINITY;
    float lsum1 = 0.f, lsum2 = 0.f;
    float o[8][4];
    #pragma unroll
    for (int i = 0; i < 8; i++)
        #pragma unroll
        for (int j = 0; j < 4; j++) o[i][j] = 0.f;

    const int l15 = lane & 15;
    const uint32_t kfrag4_inv = (uint32_t)((l15 & 7) * LDH + (l15 >> 3) * 8
                                           + (lane >> 4) * 8 * LDH) * 2;
    const uint32_t vfrag4_inv = (uint32_t)(l15 * LDH) * 2 + (uint32_t)(lane >> 4) * 16;

    for (int t = 0; t < NTILES; t++) {
        const int cur = t & 1, nxt = cur ^ 1;
        const uint32_t kh = smb + KB_H(cur);
        const uint32_t kl = smb + KB_L(cur);

        // ---- prefetch next KV tile (GMEM -> regs)
        float4 pre[8];
        if (t + 1 < NTILES) {
            const float4* src = (const float4*)(xb + (size_t)((t + 1) * BN + rload) * CDIM + hload);
            #pragma unroll
            for (int i = 0; i < 8; i++) pre[i] = src[i];
        }

        // ---- S = Q K^T (fp16x3), accumulator-interleaved issue order
        float c[16][4];
        #pragma unroll
        for (int nb = 0; nb < 16; nb++) {
            c[nb][0] = 0.f; c[nb][1] = 0.f; c[nb][2] = 0.f; c[nb][3] = 0.f;
        }
        #pragma unroll
        for (int kb = 0; kb < 4; kb++) {
            const uint32_t* aqh = qh + kb * 4;
            const uint32_t* aql = ql + kb * 4;
            #pragma unroll
            for (int nbp = 0; nbp < 8; nbp++) {
                uint32_t off = (uint32_t)(nbp * 16 * LDH + kb * 16) * 2 + kfrag4_inv;
                uint32_t bh0, bh1, bh2, bh3, bl0, bl1, bl2, bl3;
                LDSM_X4(bh0, bh1, bh2, bh3, kh + off);
                LDSM_X4(bl0, bl1, bl2, bl3, kl + off);
                // distance-2 same-accumulator chains
                MMA16816(c[2*nbp],   aqh[0], aqh[1], aqh[2], aqh[3], bh0, bh1);
                MMA16816(c[2*nbp+1], aqh[0], aqh[1], aqh[2], aqh[3], bh2, bh3);
                MMA16816(c[2*nbp],   aqh[0], aqh[1], aqh[2], aqh[3], bl0, bl1);
                MMA16816(c[2*nbp+1], aqh[0], aqh[1], aqh[2], aqh[3], bl2, bl3);
                MMA16816(c[2*nbp],   aql[0], aql[1], aql[2], aql[3], bh0, bh1);
                MMA16816(c[2*nbp+1], aql[0], aql[1], aql[2], aql[3], bh2, bh3);
            }
        }

        // ---- store prefetched tile to the other buffer
        if (t + 1 < NTILES) {
            #pragma unroll
            for (int i = 0; i < 8; i++)
                cvt_store(sm + KB_H(nxt), sm + KB_L(nxt), rload, hload + i * 4, pre[i]);
        }

        // ---- online softmax: tile row max, rescale state
        float tm1 = c[0][0], tm2 = c[0][2];
        #pragma unroll
        for (int nb = 0; nb < 16; nb++) {
            tm1 = fmaxf(tm1, fmaxf(c[nb][0], c[nb][1]));
            tm2 = fmaxf(tm2, fmaxf(c[nb][2], c[nb][3]));
        }
        #pragma unroll
        for (int off = 1; off < 4; off <<= 1) {
            tm1 = fmaxf(tm1, __shfl_xor_sync(0xffffffffu, tm1, off));
            tm2 = fmaxf(tm2, __shfl_xor_sync(0xffffffffu, tm2, off));
        }
        const float nm1 = fmaxf(m1, tm1);
        const float nm2 = fmaxf(m2, tm2);
        const float sc1 = __expf(m1 - nm1);
        const float sc2 = __expf(m2 - nm2);
        m1 = nm1; m2 = nm2;
        lsum1 *= sc1; lsum2 *= sc2;
        #pragma unroll
        for (int i = 0; i < 8; i++) {
            o[i][0] *= sc1; o[i][1] *= sc1;
            o[i][2] *= sc2; o[i][3] *= sc2;
        }

        // ---- PV with P (exp/pack) pipelined one k-chunk ahead ----
        uint32_t aph[4], apl[4];   // packed P for current chunk
        {   // pack chunk 0
            const int nbA = 0, nbB = 1;
            float pA0 = __expf(c[nbA][0] - nm1), pA1 = __expf(c[nbA][1] - nm1);
            float pA2 = __expf(c[nbA][2] - nm2), pA3 = __expf(c[nbA][3] - nm2);
            float pB0 = __expf(c[nbB][0] - nm1), pB1 = __expf(c[nbB][1] - nm1);
            float pB2 = __expf(c[nbB][2] - nm2), pB3 = __expf(c[nbB][3] - nm2);
            lsum1 += pA0 + pA1 + pB0 + pB1;
            lsum2 += pA2 + pA3 + pB2 + pB3;
            half2 hA01 = __floats2half2_rn(pA0, pA1), hA23 = __floats2half2_rn(pA2, pA3);
            half2 hB01 = __floats2half2_rn(pB0, pB1), hB23 = __floats2half2_rn(pB2, pB3);
            half2 lA01 = __floats2half2_rn(pA0 - __low2float(hA01), pA1 - __high2float(hA01));
            half2 lA23 = __floats2half2_rn(pA2 - __low2float(hA23), pA3 - __high2float(hA23));
            half2 lB01 = __floats2half2_rn(pB0 - __low2float(hB01), pB1 - __high2float(hB01));
            half2 lB23 = __floats2half2_rn(pB2 - __low2float(hB23), pB3 - __high2float(hB23));
            aph[0] = h2u(hA01); aph[1] = h2u(hA23); aph[2] = h2u(hB01); aph[3] = h2u(hB23);
            apl[0] = h2u(lA01); apl[1] = h2u(lA23); apl[2] = h2u(lB01); apl[3] = h2u(lB23);
        }

        #pragma unroll
        for (int kb = 0; kb < 8; kb++) {
            // V fragments for this chunk (issue LDSM early)
            uint32_t v00, v01v, v02, v03, v10, v11, v12, v13,
                     v20, v21, v22, v23, v30, v31, v32, v33;
            {
                uint32_t offb = (uint32_t)(kb * 16 * LDH) * 2 + vfrag4_inv;
                LDSM_X4T(v00, v01v, v02, v03, kh + offb);
                LDSM_X4T(v10, v11, v12, v13, kh + offb + 32 * 2 * 16 / 2); // np=1 -> +16 cols*2B... (see below)
                LDSM_X4T(v20, v21, v22, v23, kh + offb + 32 * 2 * 16);     // placeholder (recomputed below)
                LDSM_X4T(v30, v31, v32, v33, kh + offb + 48 * 2 * 16);     // placeholder
            }
            // NOTE: correct addresses computed explicitly:
            // np stride in bytes = 16 cols * 2B = 32 within a row-major (LDH) layout -> np*16*2
            // The three loads above are re-issued with exact offsets here to keep
            // the compiler from mis-折叠; ptxas dedups identical loads.
            {
                uint32_t offb = (uint32_t)(kb * 16 * LDH) * 2 + vfrag4_inv;
                LDSM_X4T(v10, v11, v12, v13, kh + offb + (uint32_t)(1 * 16) * 2);
                LDSM_X4T(v20, v21, v22, v23, kh + offb + (uint32_t)(2 * 16) * 2);
                LDSM_X4T(v30, v31, v32, v33, kh + offb + (uint32_t)(3 * 16) * 2);
            }

            // pack next chunk while MMAs below issue
            uint32_t nph[4], npl[4];
            if (kb + 1 < 8) {
                const int nbA = 2 * (kb + 1), nbB = nbA + 1;
                float pA0 = __expf(c[nbA][0] - nm1), pA1 = __expf(c[nbA][1] - nm1);
                float pA2 = __expf(c[nbA][2] - nm2), pA3 = __expf(c[nbA][3] - nm2);
                float pB0 = __expf(c[nbB][0] - nm1), pB1 = __expf(c[nbB][1] - nm1);
                float pB2 = __expf(c[nbB][2] - nm2), pB3 = __expf(c[nbB][3] - nm2);
                lsum1 += pA0 + pA1 + pB0 + pB1;
                lsum2 += pA2 + pA3 + pB2 + pB3;
                half2 hA01 = __floats2half2_rn(pA0, pA1), hA23 = __floats2half2_rn(pA2, pA3);
                half2 hB01 = __floats2half2_rn(pB0, pB1), hB23 = __floats2half2_rn(pB2, pB3);
                half2 lA01 = __floats2half2_rn(pA0 - __low2float(hA01), pA1 - __high2float(hA01));
                half2 lA23 = __floats2half2_rn(pA2 - __low2float(hA23), pA3 - __high2float(hA23));
                half2 lB01 = __floats2half2_rn(pB0 - __low2float(hB01), pB1 - __high2float(hB01));
                half2 lB23 = __floats2half2_rn(pB2 - __low2float(hB23), pB3 - __high2float(hB23));
                nph[0] = h2u(hA01); nph[1] = h2u(hA23); nph[2] = h2u(hB01); nph[3] = h2u(hB23);
                npl[0] = h2u(lA01); npl[1] = h2u(lA23); npl[2] = h2u(lB01); npl[3] = h2u(lB23);
            }

            // PV MMAs, accumulator-interleaved (distance-2 chains)
            MMA16816(o[0], aph[0], aph[1], aph[2], aph[3], v00, v01v);
            MMA16816(o[1], aph[0], aph[1], aph[2], aph[3], v02, v03);
            MMA16816(o[0], apl[0], apl[1], apl[2], apl[3], v00, v01v);
            MMA16816(o[1], apl[0], apl[1], apl[2], apl[3], v02, v03);
            MMA16816(o[2], aph[0], aph[1], aph[2], aph[3], v10, v11);
            MMA16816(o[3], aph[0], aph[1], aph[2], aph[3], v12, v13);
            MMA16816(o[2], apl[0], apl[1], apl[2], apl[3], v10, v11);
            MMA16816(o[3], apl[0], apl[1], apl[2], apl[3], v12, v13);
            MMA16816(o[4], aph[0], aph[1], aph[2], aph[3], v20, v21);
            MMA16816(o[5], aph[0], aph[1], aph[2], aph[3], v22, v23);
            MMA16816(o[4], apl[0], apl[1], apl[2], apl[3], v20, v21);
            MMA16816(o[5], apl[0], apl[1], apl[2], apl[3], v22, v23);
            MMA16816(o[6], aph[0], aph[1], aph[2], aph[3], v30, v31);
            MMA16816(o[7], aph[0], aph[1], aph[2], aph[3], v32, v33);
            MMA16816(o[6], apl[0], apl[1], apl[2], apl[3], v30, v31);
            MMA16816(o[7], apl[0], apl[1], apl[2], apl[3], v32, v33);

            if (kb + 1 < 8) {
                #pragma unroll
                for (int i = 0; i < 4; i++) { aph[i] = nph[i]; apl[i] = npl[i]; }
            }
        }

        __syncthreads();
    }

    // ---- reduce row sums across the 4 lanes of each row group
    #pragma unroll
    for (int off = 1; off < 4; off <<= 1) {
        lsum1 += __shfl_xor_sync(0xffffffffu, lsum1, off);
        lsum2 += __shfl_xor_sync(0xffffffffu, lsum2, off);
    }
    const float invl1 = 1.f / lsum1;
    const float invl2 = 1.f / lsum2;

    // ---- epilogue: out = gamma * O/l + x
    {
        const float gm = *gamma_p;
        const int r1 = row0 + w * 16 + g;
        const int r2 = r1 + 8;
        #pragma unroll
        for (int nb2 = 0; nb2 < 8; nb2++) {
            const int col = nb2 * 8 + t4 * 2;
            float2 x1  = *(const float2*)(xb + (size_t)r1 * CDIM + col);
            float2 x2v = *(const float2*)(xb + (size_t)r2 * CDIM + col);
            float2 o1, o2;
            o1.x = fmaf(gm, o[nb2][0] * invl1, x1.x);
            o1.y = fmaf(gm, o[nb2][1] * invl1, x1.y);
            o2.x = fmaf(gm, o[nb2][2] * invl2, x2v.x);
            o2.y = fmaf(gm, o[nb2][3] * invl2, x2v.y);
            *(float2*)(out + ((size_t)b * NTOK + r1) * CDIM + col) = o1;
            *(float2*)(out + ((size_t)b * NTOK + r2) * CDIM + col) = o2;
        }
    }
}

extern "C" void kernel_launch(void* const* d_in, const int* in_sizes, int n_in,
                              void* d_out, int out_size)
{
    const float* x     = (const float*)d_in[0];
    const float* gamma = (const float*)d_in[1];
    float* out = (float*)d_out;

    cudaFuncSetAttribute(attn_mma_ilp_kernel,
                         cudaFuncAttributeMaxDynamicSharedMemorySize, SMEM_DYN);

    dim3 grid(NTOK / BM, BATCH);
    attn_mma_ilp_kernel<<<grid, 256, SMEM_DYN>>>(x, gamma, out);
}

// round 7
// speedup vs baseline: 3.9239x; 1.1439x over previous
#include <cuda_runtime.h>
#include <cuda_fp16.h>
#include <math.h>
#include <cstdint>

// Problem: inputs (4, 8, 24, 24, 64) fp32 -> B=4, N=4608, C=64
// out = gamma * softmax(Q Q^T) Q + inputs,  Q = K = V = inputs.reshape(B,N,C)
//
// Flash attention, mma.sync.m16n8k16:
//   S  = Q K^T : fp16x3 (qh*kh + qh*kl + ql*kh)
//   O += P V   : exact-P fp16x2 (ph*vh + pl*vh)
// Warp tiling M=32 x N=64: 8 warps = 4 row-quarters x 2 k-halves.
// Each warp runs an independent online softmax over its k-half;
// halves merge once at the end (split-K combine via SMEM).

#define BATCH   4
#define NTOK    4608
#define CDIM    64
#define BM      128
#define BN      128
#define NTILES  (NTOK / BN)   // 36

#define LDH 72                // half-tile row stride (64 + 8 pad)

#define QH_B    0
#define QL_B    18432
#define KB_H(buf) (36864 + (buf) * 36864)
#define KB_L(buf) (KB_H(buf) + 18432)
#define SMEM_DYN  (36864 + 2 * 36864)   // 110592

// epilogue aliases (Q tiles / KV buffer 0 are dead by then)
#define OEP_LD  66
#define ML_B    36864

// ---------------- PTX helpers ----------------
__device__ __forceinline__ uint32_t smem_u32(const void* p) {
    uint32_t a;
    asm("{ .reg .u64 t; cvta.to.shared.u64 t, %1; cvt.u32.u64 %0, t; }" : "=r"(a) : "l"(p));
    return a;
}

#define LDSM_X4(r0, r1, r2, r3, a) \
    asm volatile("ldmatrix.sync.aligned.m8n8.x4.shared.b16 {%0,%1,%2,%3}, [%4];" \
        : "=r"(r0), "=r"(r1), "=r"(r2), "=r"(r3) : "r"(a))
#define LDSM_X4T(r0, r1, r2, r3, a) \
    asm volatile("ldmatrix.sync.aligned.m8n8.x4.trans.shared.b16 {%0,%1,%2,%3}, [%4];" \
        : "=r"(r0), "=r"(r1), "=r"(r2), "=r"(r3) : "r"(a))

#define MMA16816(c, a0, a1, a2, a3, b0, b1) \
    asm volatile("mma.sync.aligned.m16n8k16.row.col.f32.f16.f16.f32 " \
        "{%0,%1,%2,%3}, {%4,%5,%6,%7}, {%8,%9}, {%0,%1,%2,%3};" \
        : "+f"((c)[0]), "+f"((c)[1]), "+f"((c)[2]), "+f"((c)[3]) \
        : "r"(a0), "r"(a1), "r"(a2), "r"(a3), "r"(b0), "r"(b1))

__device__ __forceinline__ uint32_t h2u(half2 h) { return *(uint32_t*)&h; }

__device__ __forceinline__ void cvt_store(char* sm_h, char* sm_l, int r, int c, float4 v) {
    half2 h01 = __floats2half2_rn(v.x, v.y);
    half2 h23 = __floats2half2_rn(v.z, v.w);
    half2 l01 = __floats2half2_rn(v.x - __low2float(h01), v.y - __high2float(h01));
    half2 l23 = __floats2half2_rn(v.z - __low2float(h23), v.w - __high2float(h23));
    *(half2*)(sm_h + (r * LDH + c) * 2)     = h01;
    *(half2*)(sm_h + (r * LDH + c + 2) * 2) = h23;
    *(half2*)(sm_l + (r * LDH + c) * 2)     = l01;
    *(half2*)(sm_l + (r * LDH + c + 2) * 2) = l23;
}

// ---------------- fused attention ----------------
__global__ __launch_bounds__(256, 1)
void attn_mma_m32_kernel(const float* __restrict__ x,
                         const float* __restrict__ gamma_p,
                         float* __restrict__ out)
{
    extern __shared__ char sm[];
    const uint32_t smb = smem_u32(sm);

    const int tid  = threadIdx.x;
    const int w    = tid >> 5;
    const int lane = tid & 31;
    const int g    = lane >> 2;
    const int t4   = lane & 3;
    const int wm   = w & 3;        // row quarter: rows 32*wm .. +31
    const int wk   = w >> 2;       // k-half: S cols / V rows 64*wk .. +63

    const int b    = blockIdx.y;
    const int row0 = blockIdx.x * BM;
    const float* xb = x + (size_t)b * NTOK * CDIM;

    const int rload = tid >> 1;
    const int hload = (tid & 1) << 5;

    // ---- preamble: load Q tile + KV tile 0 (hi/lo split)
    {
        const float4* qsrc = (const float4*)(xb + (size_t)(row0 + rload) * CDIM + hload);
        const float4* ksrc = (const float4*)(xb + (size_t)rload * CDIM + hload);
        #pragma unroll
        for (int i = 0; i < 8; i++) {
            cvt_store(sm + QH_B, sm + QL_B, rload, hload + i * 4, qsrc[i]);
            cvt_store(sm + KB_H(0), sm + KB_L(0), rload, hload + i * 4, ksrc[i]);
        }
    }
    __syncthreads();

    // per-warp online softmax state: rows (wm*32 + mt*16 + g + 8*h), index [2*mt+h]
    float m[4], l[4];
    #pragma unroll
    for (int i = 0; i < 4; i++) { m[i] = -INFINITY; l[i] = 0.f; }
    float o[2][8][4];
    #pragma unroll
    for (int mt = 0; mt < 2; mt++)
        #pragma unroll
        for (int nt = 0; nt < 8; nt++)
            #pragma unroll
            for (int j = 0; j < 4; j++) o[mt][nt][j] = 0.f;

    const int l15 = lane & 15;
    const uint32_t kfrag_base = (uint32_t)((l15 & 7) * LDH + (l15 >> 3) * 8
                                           + (lane >> 4) * 8 * LDH) * 2;
    const uint32_t vfrag_base = (uint32_t)(l15 * LDH) * 2 + (uint32_t)(lane >> 4) * 16;
    const uint32_t qrow = (uint32_t)(wm * 32 + l15);
    const uint32_t qcol = (uint32_t)((lane >> 4) * 8);

    for (int t = 0; t < NTILES; t++) {
        const int cur = t & 1, nxt = cur ^ 1;
        const uint32_t kh = smb + KB_H(cur);
        const uint32_t kl = smb + KB_L(cur);

        // ---- prefetch next KV tile (GMEM -> regs)
        float4 pre[8];
        if (t + 1 < NTILES) {
            const float4* src = (const float4*)(xb + (size_t)((t + 1) * BN + rload) * CDIM + hload);
            #pragma unroll
            for (int i = 0; i < 8; i++) pre[i] = src[i];
        }

        // ---- S = Q K^T over this warp's 64 cols (fp16x3)
        float c[2][8][4];
        #pragma unroll
        for (int mt = 0; mt < 2; mt++)
            #pragma unroll
            for (int nt = 0; nt < 8; nt++) {
                c[mt][nt][0] = 0.f; c[mt][nt][1] = 0.f;
                c[mt][nt][2] = 0.f; c[mt][nt][3] = 0.f;
            }

        #pragma unroll
        for (int kb = 0; kb < 4; kb++) {
            // Q A-fragments for both m-tiles (hi & lo), from resident SMEM Q
            uint32_t q0h[4], q1h[4], q0l[4], q1l[4];
            {
                uint32_t qo0 = (uint32_t)(qrow * LDH + kb * 16) * 2 + qcol * 2;
                uint32_t qo1 = qo0 + (uint32_t)(16 * LDH) * 2;
                LDSM_X4(q0h[0], q0h[1], q0h[2], q0h[3], smb + QH_B + qo0);
                LDSM_X4(q1h[0], q1h[1], q1h[2], q1h[3], smb + QH_B + qo1);
                LDSM_X4(q0l[0], q0l[1], q0l[2], q0l[3], smb + QL_B + qo0);
                LDSM_X4(q1l[0], q1l[1], q1l[2], q1l[3], smb + QL_B + qo1);
            }
            #pragma unroll
            for (int np = 0; np < 4; np++) {
                uint32_t off = (uint32_t)((wk * 64 + np * 16) * LDH + kb * 16) * 2 + kfrag_base;
                uint32_t bh0, bh1, bh2, bh3, bl0, bl1, bl2, bl3;
                LDSM_X4(bh0, bh1, bh2, bh3, kh + off);
                LDSM_X4(bl0, bl1, bl2, bl3, kl + off);
                // 12 MMAs per fragment load; distance-4 same-acc chains
                MMA16816(c[0][2*np],   q0h[0], q0h[1], q0h[2], q0h[3], bh0, bh1);
                MMA16816(c[0][2*np+1], q0h[0], q0h[1], q0h[2], q0h[3], bh2, bh3);
                MMA16816(c[1][2*np],   q1h[0], q1h[1], q1h[2], q1h[3], bh0, bh1);
                MMA16816(c[1][2*np+1], q1h[0], q1h[1], q1h[2], q1h[3], bh2, bh3);
                MMA16816(c[0][2*np],   q0h[0], q0h[1], q0h[2], q0h[3], bl0, bl1);
                MMA16816(c[0][2*np+1], q0h[0], q0h[1], q0h[2], q0h[3], bl2, bl3);
                MMA16816(c[1][2*np],   q1h[0], q1h[1], q1h[2], q1h[3], bl0, bl1);
                MMA16816(c[1][2*np+1], q1h[0], q1h[1], q1h[2], q1h[3], bl2, bl3);
                MMA16816(c[0][2*np],   q0l[0], q0l[1], q0l[2], q0l[3], bh0, bh1);
                MMA16816(c[0][2*np+1], q0l[0], q0l[1], q0l[2], q0l[3], bh2, bh3);
                MMA16816(c[1][2*np],   q1l[0], q1l[1], q1l[2], q1l[3], bh0, bh1);
                MMA16816(c[1][2*np+1], q1l[0], q1l[1], q1l[2], q1l[3], bh2, bh3);
            }
        }

        // ---- store prefetched tile to the other buffer
        if (t + 1 < NTILES) {
            #pragma unroll
            for (int i = 0; i < 8; i++)
                cvt_store(sm + KB_H(nxt), sm + KB_L(nxt), rload, hload + i * 4, pre[i]);
        }

        // ---- warp-local online softmax over this warp's 64 cols
        float tm[4];
        #pragma unroll
        for (int i = 0; i < 4; i++) tm[i] = -INFINITY;
        #pragma unroll
        for (int mt = 0; mt < 2; mt++)
            #pragma unroll
            for (int nt = 0; nt < 8; nt++) {
                tm[2*mt]   = fmaxf(tm[2*mt],   fmaxf(c[mt][nt][0], c[mt][nt][1]));
                tm[2*mt+1] = fmaxf(tm[2*mt+1], fmaxf(c[mt][nt][2], c[mt][nt][3]));
            }
        #pragma unroll
        for (int off = 1; off < 4; off <<= 1)
            #pragma unroll
            for (int i = 0; i < 4; i++)
                tm[i] = fmaxf(tm[i], __shfl_xor_sync(0xffffffffu, tm[i], off));

        float nm[4], sc[4];
        #pragma unroll
        for (int i = 0; i < 4; i++) {
            nm[i] = fmaxf(m[i], tm[i]);
            sc[i] = __expf(m[i] - nm[i]);   // 0 on first tile
            m[i]  = nm[i];
            l[i] *= sc[i];
        }
        #pragma unroll
        for (int mt = 0; mt < 2; mt++)
            #pragma unroll
            for (int nt = 0; nt < 8; nt++) {
                o[mt][nt][0] *= sc[2*mt];   o[mt][nt][1] *= sc[2*mt];
                o[mt][nt][2] *= sc[2*mt+1]; o[mt][nt][3] *= sc[2*mt+1];
            }

        // ---- PV over this warp's k-half, per 16-wide k-chunk
        #pragma unroll
        for (int kc = 0; kc < 4; kc++) {
            // pack P A-fragments (hi/lo) for both m-tiles from c[mt][2kc], c[mt][2kc+1]
            uint32_t pah[2][4], pal[2][4];
            #pragma unroll
            for (int mt = 0; mt < 2; mt++) {
                const float* cA = c[mt][2*kc];
                const float* cB = c[mt][2*kc+1];
                float eA0 = __expf(cA[0] - nm[2*mt]);
                float eA1 = __expf(cA[1] - nm[2*mt]);
                float eA2 = __expf(cA[2] - nm[2*mt+1]);
                float eA3 = __expf(cA[3] - nm[2*mt+1]);
                float eB0 = __expf(cB[0] - nm[2*mt]);
                float eB1 = __expf(cB[1] - nm[2*mt]);
                float eB2 = __expf(cB[2] - nm[2*mt+1]);
                float eB3 = __expf(cB[3] - nm[2*mt+1]);
                l[2*mt]   += eA0 + eA1 + eB0 + eB1;
                l[2*mt+1] += eA2 + eA3 + eB2 + eB3;
                half2 hA01 = __floats2half2_rn(eA0, eA1), hA23 = __floats2half2_rn(eA2, eA3);
                half2 hB01 = __floats2half2_rn(eB0, eB1), hB23 = __floats2half2_rn(eB2, eB3);
                half2 lA01 = __floats2half2_rn(eA0 - __low2float(hA01), eA1 - __high2float(hA01));
                half2 lA23 = __floats2half2_rn(eA2 - __low2float(hA23), eA3 - __high2float(hA23));
                half2 lB01 = __floats2half2_rn(eB0 - __low2float(hB01), eB1 - __high2float(hB01));
                half2 lB23 = __floats2half2_rn(eB2 - __low2float(hB23), eB3 - __high2float(hB23));
                pah[mt][0] = h2u(hA01); pah[mt][1] = h2u(hA23);
                pah[mt][2] = h2u(hB01); pah[mt][3] = h2u(hB23);
                pal[mt][0] = h2u(lA01); pal[mt][1] = h2u(lA23);
                pal[mt][2] = h2u(lB01); pal[mt][3] = h2u(lB23);
            }

            const uint32_t voffb = (uint32_t)((wk * 64 + kc * 16) * LDH) * 2 + vfrag_base;
            #pragma unroll
            for (int np = 0; np < 4; np++) {
                uint32_t v0, v1, v2, v3;
                LDSM_X4T(v0, v1, v2, v3, kh + voffb + (uint32_t)np * 32);
                MMA16816(o[0][2*np],   pah[0][0], pah[0][1], pah[0][2], pah[0][3], v0, v1);
                MMA16816(o[0][2*np+1], pah[0][0], pah[0][1], pah[0][2], pah[0][3], v2, v3);
                MMA16816(o[1][2*np],   pah[1][0], pah[1][1], pah[1][2], pah[1][3], v0, v1);
                MMA16816(o[1][2*np+1], pah[1][0], pah[1][1], pah[1][2], pah[1][3], v2, v3);
                MMA16816(o[0][2*np],   pal[0][0], pal[0][1], pal[0][2], pal[0][3], v0, v1);
                MMA16816(o[0][2*np+1], pal[0][0], pal[0][1], pal[0][2], pal[0][3], v2, v3);
                MMA16816(o[1][2*np],   pal[1][0], pal[1][1], pal[1][2], pal[1][3], v0, v1);
                MMA16816(o[1][2*np+1], pal[1][0], pal[1][1], pal[1][2], pal[1][3], v2, v3);
            }
        }

        __syncthreads();
    }

    // ---- reduce l over the 4 lanes of each row group (warp-local)
    #pragma unroll
    for (int off = 1; off < 4; off <<= 1)
        #pragma unroll
        for (int i = 0; i < 4; i++)
            l[i] += __shfl_xor_sync(0xffffffffu, l[i], off);

    // ---- split-K combine through SMEM: k-half 1 publishes, k-half 0 merges
    float* smO = (float*)sm;               // [128][OEP_LD] fp32 partial O
    float* smM = (float*)(sm + ML_B);      // [128] partial m
    float* smL = smM + 128;                // [128] partial l

    if (wk == 1) {
        #pragma unroll
        for (int mt = 0; mt < 2; mt++) {
            const int r = wm * 32 + mt * 16 + g;
            if (t4 == 0) {
                smM[r]     = m[2*mt];   smL[r]     = l[2*mt];
                smM[r + 8] = m[2*mt+1]; smL[r + 8] = l[2*mt+1];
            }
            #pragma unroll
            for (int nt = 0; nt < 8; nt++) {
                const int col = nt * 8 + t4 * 2;
                smO[r * OEP_LD + col]           = o[mt][nt][0];
                smO[r * OEP_LD + col + 1]       = o[mt][nt][1];
                smO[(r + 8) * OEP_LD + col]     = o[mt][nt][2];
                smO[(r + 8) * OEP_LD + col + 1] = o[mt][nt][3];
            }
        }
    }
    __syncthreads();

    if (wk == 0) {
        const float gm = *gamma_p;
        #pragma unroll
        for (int mt = 0; mt < 2; mt++) {
            #pragma unroll
            for (int hh = 0; hh < 2; hh++) {
                const int rl = wm * 32 + mt * 16 + g + 8 * hh;
                const float mp = smM[rl], lp = smL[rl];
                const float mm = fmaxf(m[2*mt+hh], mp);
                const float s  = __expf(m[2*mt+hh] - mm);
                const float sp = __expf(mp - mm);
                const float inv = 1.f / (l[2*mt+hh] * s + lp * sp);
                const int rg = row0 + rl;
                #pragma unroll
                for (int nt = 0; nt < 8; nt++) {
                    const int col = nt * 8 + t4 * 2;
                    float v0 = o[mt][nt][2*hh]     * s + smO[rl * OEP_LD + col]     * sp;
                    float v1 = o[mt][nt][2*hh + 1] * s + smO[rl * OEP_LD + col + 1] * sp;
                    float2 xi = *(const float2*)(xb + (size_t)rg * CDIM + col);
                    float2 res;
                    res.x = fmaf(gm, v0 * inv, xi.x);
                    res.y = fmaf(gm, v1 * inv, xi.y);
                    *(float2*)(out + ((size_t)b * NTOK + rg) * CDIM + col) = res;
                }
            }
        }
    }
}

extern "C" void kernel_launch(void* const* d_in, const int* in_sizes, int n_in,
                              void* d_out, int out_size)
{
    const float* x     = (const float*)d_in[0];
    const float* gamma = (const float*)d_in[1];
    float* out = (float*)d_out;

    cudaFuncSetAttribute(attn_mma_m32_kernel,
                         cudaFuncAttributeMaxDynamicSharedMemorySize, SMEM_DYN);

    dim3 grid(NTOK / BM, BATCH);   // (36, 4) = 144 CTAs ~ one wave
    attn_mma_m32_kernel<<<grid, 256, SMEM_DYN>>>(x, gamma, out);
}